// round 14
// baseline (speedup 1.0000x reference)
#include <cuda_runtime.h>

#define N 512
#define D 512

__device__ float g_u[N * D];            // u[i][h]
__device__ float g_vT[D * N];           // v^T[h][j] (+W0_b folded)
__device__ float g_a[N * N];            // softmax rows
__device__ float g_part[4 * N * 1024];  // k-split partials

typedef unsigned long long u64;

// ---- packed f32x2 helpers (sm_100+) --------------------------------------
__device__ __forceinline__ void fma2(u64& d, u64 a, u64 b) {
    asm("fma.rn.f32x2 %0, %1, %2, %3;" : "=l"(d) : "l"(a), "l"(b), "l"(d));
}
__device__ __forceinline__ u64 add2(u64 a, u64 b) {
    u64 d; asm("add.rn.f32x2 %0, %1, %2;" : "=l"(d) : "l"(a), "l"(b)); return d;
}
__device__ __forceinline__ u64 pk(float x, float y) {
    u64 d; asm("mov.b64 %0, {%1, %2};" : "=l"(d) : "f"(x), "f"(y)); return d;
}
__device__ __forceinline__ float2 upk(u64 v) {
    float2 d; asm("mov.b64 {%0, %1}, %2;" : "=f"(d.x), "=f"(d.y) : "l"(v)); return d;
}
__device__ __forceinline__ void cpa16(float* dst, const float* src) {
    unsigned sa = (unsigned)__cvta_generic_to_shared(dst);
    asm volatile("cp.async.cg.shared.global [%0], [%1], 16;" :: "r"(sa), "l"(src));
}

// ---------------------------------------------------------------------------
// Kernel 1: fused u|v GEMM, k-split 4. Tile 128x128, 512 threads (16 warps),
// thread 8x4 (k-pair packed FFMA2; av warp-uniform broadcast). grid
// (8,4,4)=128 CTAs.
// ---------------------------------------------------------------------------
#define GST 36

__global__ __launch_bounds__(512) void uv_gemm_kernel(
    const float* __restrict__ he, const float* __restrict__ W)
{
    extern __shared__ float sm[];
    float* as = sm;                    // [2][128*GST]
    float* bs = sm + 2 * 128 * GST;    // [2][128*GST]

    const int n0 = blockIdx.x * 128;
    const int i0 = blockIdx.y * 128;
    const int kz = blockIdx.z;
    const int kbase = kz * 128;
    const int koff = (n0 >= 512) ? 512 : 0;
    const int nrow0 = n0 & 511;
    const int tid = threadIdx.x;
    const int tx = tid & 31;           // col base: tx + 32c
    const int ty = tid >> 5;           // row base: ty + 16r (warp-uniform)

    // prologue chunk 0: per matrix 1024 f4, 2 per thread
    #pragma unroll
    for (int q = 0; q < 2; q++) {
        const int f = tid + 512 * q;
        const int r = f >> 3, kq = (f & 7) << 2;
        cpa16(&as[r * GST + kq], &he[(size_t)(i0 + r) * D + kbase + kq]);
        cpa16(&bs[r * GST + kq], &W[(size_t)(nrow0 + r) * (2 * D) + koff + kbase + kq]);
    }
    asm volatile("cp.async.commit_group;");

    u64 acc[8][4] = {};

    for (int ch = 0; ch < 4; ch++) {
        if (ch + 1 < 4) {
            float* ad = as + ((ch + 1) & 1) * 128 * GST;
            float* bd = bs + ((ch + 1) & 1) * 128 * GST;
            const int kc = kbase + (ch + 1) * 32;
            #pragma unroll
            for (int q = 0; q < 2; q++) {
                const int f = tid + 512 * q;
                const int r = f >> 3, kq = (f & 7) << 2;
                cpa16(&ad[r * GST + kq], &he[(size_t)(i0 + r) * D + kc + kq]);
                cpa16(&bd[r * GST + kq], &W[(size_t)(nrow0 + r) * (2 * D) + koff + kc + kq]);
            }
            asm volatile("cp.async.commit_group;");
            asm volatile("cp.async.wait_group 1;");
        } else {
            asm volatile("cp.async.wait_group 0;");
        }
        __syncthreads();

        const float* ab = as + (ch & 1) * 128 * GST;
        const float* bb = bs + (ch & 1) * 128 * GST;
        #pragma unroll
        for (int kk = 0; kk < 32; kk += 2) {
            u64 av[8], bv[4];
            #pragma unroll
            for (int r = 0; r < 8; r++)
                av[r] = *(const u64*)&ab[(ty + 16 * r) * GST + kk];
            #pragma unroll
            for (int c = 0; c < 4; c++)
                bv[c] = *(const u64*)&bb[(tx + 32 * c) * GST + kk];
            #pragma unroll
            for (int r = 0; r < 8; r++)
                #pragma unroll
                for (int c = 0; c < 4; c++)
                    fma2(acc[r][c], av[r], bv[c]);
        }
        __syncthreads();
    }

    #pragma unroll
    for (int r = 0; r < 8; r++) {
        const size_t row = i0 + ty + 16 * r;
        float* dst = g_part + (size_t)kz * (N * 1024) + row * 1024 + n0;
        #pragma unroll
        for (int c = 0; c < 4; c++) {
            float2 f = upk(acc[r][c]);
            dst[tx + 32 * c] = f.x + f.y;
        }
    }
}

// ---------------------------------------------------------------------------
// Kernel 2: reduce k-split partials -> g_u, g_vT (+bias). grid 512 x 256,
// one float4 per thread. Deterministic.
// ---------------------------------------------------------------------------
__global__ __launch_bounds__(256) void reduce_kernel(const float* __restrict__ b)
{
    const int idx4 = blockIdx.x * 256 + threadIdx.x;   // 0..131071
    float4 s = *(const float4*)&g_part[(size_t)idx4 * 4];
    #pragma unroll
    for (int kz = 1; kz < 4; kz++) {
        float4 p = *(const float4*)&g_part[(size_t)kz * (N * 1024) + (size_t)idx4 * 4];
        s.x += p.x; s.y += p.y; s.z += p.z; s.w += p.w;
    }
    const int base = idx4 * 4;
    const int i = base >> 10;
    const int h = base & 1023;
    if (h < 512) {
        *(float4*)&g_u[(size_t)i * D + h] = s;
    } else {
        const int hh = h - 512;
        g_vT[(size_t)(hh + 0) * N + i] = s.x + b[hh + 0];
        g_vT[(size_t)(hh + 1) * N + i] = s.y + b[hh + 1];
        g_vT[(size_t)(hh + 2) * N + i] = s.z + b[hh + 2];
        g_vT[(size_t)(hh + 3) * N + i] = s.w + b[hh + 3];
    }
}

// ---------------------------------------------------------------------------
// Kernel 3: pairwise + softmax. CTA = 4 i x 512 j, 512 threads (16 warps;
// thread = 2 i x 1 j-pair). v staged via cp.async (PHCH=8); u/w duplicated
// {x,x} u64 pairs read as LDS.128 over (h,h+1).
// ---------------------------------------------------------------------------
#define PHCH 8

__global__ __launch_bounds__(512) void pairwise_kernel(
    const float* __restrict__ w1)
{
    extern __shared__ float sm[];
    float* v_s   = sm;                              // [2][PHCH][512]
    u64*  u2s    = (u64*)(sm + 2 * PHCH * 512);     // [4*512]
    u64*  w2s    = u2s + 4 * 512;                   // [512]
    float* p_s   = (float*)(w2s + 512);             // [4][512]
    float* inv_s = p_s + 4 * 512;                   // [4]

    const int tid = threadIdx.x;
    const int i0 = blockIdx.x * 4;
    const int g = tid >> 8;                         // i rows {2g, 2g+1}
    const int jp = tid & 255;                       // j-pair index

    // stage u (4 rows) and w1 as duplicated {x,x} pairs
    {
        const float4* usrc = (const float4*)(g_u + (size_t)i0 * D);
        float4 f = usrc[tid];                       // 512 f4 total
        u2s[tid * 4 + 0] = pk(f.x, f.x);
        u2s[tid * 4 + 1] = pk(f.y, f.y);
        u2s[tid * 4 + 2] = pk(f.z, f.z);
        u2s[tid * 4 + 3] = pk(f.w, f.w);
        if (tid < 128) {
            float4 w = ((const float4*)w1)[tid];
            w2s[tid * 4 + 0] = pk(w.x, w.x);
            w2s[tid * 4 + 1] = pk(w.y, w.y);
            w2s[tid * 4 + 2] = pk(w.z, w.z);
            w2s[tid * 4 + 3] = pk(w.w, w.w);
        }
    }

    // prologue: v chunk 0 (PHCH x 512 = 1024 f4, 2 per thread)
    #pragma unroll
    for (int q = 0; q < 2; q++) {
        const int m = tid + 512 * q;
        const int r = m >> 7, c4 = (m & 127) << 2;
        cpa16(v_s + r * 512 + c4, g_vT + (size_t)r * N + c4);
    }
    asm volatile("cp.async.commit_group;");

    u64 acc[2] = {};

    for (int ch = 0; ch < D / PHCH; ch++) {
        if (ch + 1 < D / PHCH) {
            float* buf = v_s + ((ch + 1) & 1) * PHCH * 512;
            const float* src = g_vT + (size_t)(ch + 1) * PHCH * N;
            #pragma unroll
            for (int q = 0; q < 2; q++) {
                const int m = tid + 512 * q;
                const int r = m >> 7, c4 = (m & 127) << 2;
                cpa16(buf + r * 512 + c4, src + (size_t)r * N + c4);
            }
            asm volatile("cp.async.commit_group;");
            asm volatile("cp.async.wait_group 1;");
        } else {
            asm volatile("cp.async.wait_group 0;");
        }
        __syncthreads();

        const float* vb = v_s + (ch & 1) * PHCH * 512;
        const int g0 = ch * PHCH;
        #pragma unroll
        for (int hh = 0; hh < PHCH; hh += 2) {
            const u64 v0 = *(const u64*)&vb[hh * 512 + 2 * jp];
            const u64 v1 = *(const u64*)&vb[(hh + 1) * 512 + 2 * jp];
            const ulonglong2 ww = *(const ulonglong2*)&w2s[g0 + hh];
            #pragma unroll
            for (int ii = 0; ii < 2; ii++) {
                const ulonglong2 uu = *(const ulonglong2*)&u2s[(2 * g + ii) * 512 + g0 + hh];
                u64 t = add2(uu.x, v0);
                float2 f = upk(t);
                fma2(acc[ii], pk(fmaxf(f.x, 0.f), fmaxf(f.y, 0.f)), ww.x);
                t = add2(uu.y, v1);
                f = upk(t);
                fma2(acc[ii], pk(fmaxf(f.x, 0.f), fmaxf(f.y, 0.f)), ww.y);
            }
        }
        __syncthreads();
    }

    #pragma unroll
    for (int ii = 0; ii < 2; ii++)
        ((u64*)(p_s + (2 * g + ii) * 512))[jp] = acc[ii];
    __syncthreads();

    // softmax: warps 0..3 handle rows 0..3
    const int warp = tid >> 5, lane = tid & 31;
    if (warp < 4) {
        float* prow = p_s + warp * 512;
        float m = -1e30f;
        for (int j = lane; j < N; j += 32) m = fmaxf(m, prow[j]);
        #pragma unroll
        for (int o = 16; o; o >>= 1) m = fmaxf(m, __shfl_xor_sync(0xffffffffu, m, o));
        float s = 0.f;
        for (int j = lane; j < N; j += 32) {
            float e = __expf(prow[j] - m);
            prow[j] = e;
            s += e;
        }
        #pragma unroll
        for (int o = 16; o; o >>= 1) s += __shfl_xor_sync(0xffffffffu, s, o);
        if (lane == 0) inv_s[warp] = 1.f / s;
    }
    __syncthreads();

    {
        const int i = tid >> 7, jj = tid & 127;     // 512 f4 total
        float4 v = ((const float4*)(p_s + i * 512))[jj];
        const float s = inv_s[i];
        v.x *= s; v.y *= s; v.z *= s; v.w *= s;
        ((float4*)(g_a + (size_t)(i0 + i) * N))[jj] = v;
    }
}

// ---------------------------------------------------------------------------
// Kernel 4: out = a @ he, c-pair packed. Tile 32i x 32c, 256 threads,
// grid (16,16)=256 CTAs -> 2 CTAs/SM (16 warps). Double-buffered 32-k.
// ---------------------------------------------------------------------------
#define HST 36

__global__ __launch_bounds__(256) void out_gemm_kernel(
    const float* __restrict__ he, float* __restrict__ out)
{
    __shared__ float he_s[2][32 * HST];   // [k][c] natural rows + pad
    __shared__ u64  a2s[2][32 * 32];      // [i][k] duplicated pairs

    const int c0 = blockIdx.x * 32;
    const int i0 = blockIdx.y * 32;
    const int tid = threadIdx.x;
    const int tc = tid & 15;              // c-pair: cols 2tc, 2tc+1
    const int ti = tid >> 4;              // i rows ti, ti+16

    const int ar = tid >> 3;              // 0..31
    const int akq = (tid & 7) << 2;       // 0..28

    float areg[4];

    // prologue
    {
        float4 v = *(const float4*)&g_a[(size_t)(i0 + ar) * N + akq];
        areg[0] = v.x; areg[1] = v.y; areg[2] = v.z; areg[3] = v.w;
        ulonglong2 d0; d0.x = pk(v.x, v.x); d0.y = pk(v.y, v.y);
        ulonglong2 d1; d1.x = pk(v.z, v.z); d1.y = pk(v.w, v.w);
        *(ulonglong2*)&a2s[0][ar * 32 + akq + 0] = d0;
        *(ulonglong2*)&a2s[0][ar * 32 + akq + 2] = d1;
        const int k = tid >> 3, cq = (tid & 7) << 2;
        cpa16(&he_s[0][k * HST + cq], &he[(size_t)k * D + c0 + cq]);
        asm volatile("cp.async.commit_group;");
    }

    u64 acc[2] = {};

    for (int ch = 0; ch < 16; ch++) {
        if (ch + 1 < 16) {
            const int k0 = (ch + 1) * 32;
            float4 v = *(const float4*)&g_a[(size_t)(i0 + ar) * N + k0 + akq];
            areg[0] = v.x; areg[1] = v.y; areg[2] = v.z; areg[3] = v.w;
            const int k = tid >> 3, cq = (tid & 7) << 2;
            cpa16(&he_s[(ch + 1) & 1][k * HST + cq],
                  &he[(size_t)(k0 + k) * D + c0 + cq]);
            asm volatile("cp.async.commit_group;");
            asm volatile("cp.async.wait_group 1;");
        } else {
            asm volatile("cp.async.wait_group 0;");
        }
        __syncthreads();

        const float* hb = he_s[ch & 1];
        const u64* ab = a2s[ch & 1];
        #pragma unroll
        for (int k = 0; k < 32; k++) {
            const u64 bb = *(const u64*)&hb[k * HST + 2 * tc];
            fma2(acc[0], ab[ti * 32 + k], bb);
            fma2(acc[1], ab[(ti + 16) * 32 + k], bb);
        }

        if (ch + 1 < 16) {
            ulonglong2 d0; d0.x = pk(areg[0], areg[0]); d0.y = pk(areg[1], areg[1]);
            ulonglong2 d1; d1.x = pk(areg[2], areg[2]); d1.y = pk(areg[3], areg[3]);
            *(ulonglong2*)&a2s[(ch + 1) & 1][ar * 32 + akq + 0] = d0;
            *(ulonglong2*)&a2s[(ch + 1) & 1][ar * 32 + akq + 2] = d1;
        }
        __syncthreads();
    }

    #pragma unroll
    for (int r = 0; r < 2; r++) {
        float2 f = upk(acc[r]);
        *(float2*)&out[(size_t)(i0 + ti + 16 * r) * D + c0 + 2 * tc] = f;
    }
}

// ---------------------------------------------------------------------------
extern "C" void kernel_launch(void* const* d_in, const int* in_sizes, int n_in,
                              void* d_out, int out_size)
{
    const float* he  = (const float*)d_in[0];   // (512, 512)
    const float* W0w = (const float*)d_in[1];   // (512, 1024)
    const float* W0b = (const float*)d_in[2];   // (512,)
    const float* W1w = (const float*)d_in[3];   // (1, 512)
    // d_in[4] = W1_b: softmax shift-invariant -> unused
    float* out = (float*)d_out;

    const size_t smemG = (size_t)(4 * 128 * GST) * sizeof(float);     // ~73.7KB
    const size_t smemP = (size_t)(2 * PHCH * 512) * sizeof(float)     // v
                       + (size_t)(4 * 512 + 512) * sizeof(u64)        // u2s + w2s
                       + (size_t)(4 * 512 + 8) * sizeof(float);       // p_s + inv
    cudaFuncSetAttribute(uv_gemm_kernel,
                         cudaFuncAttributeMaxDynamicSharedMemorySize, (int)smemG);
    cudaFuncSetAttribute(pairwise_kernel,
                         cudaFuncAttributeMaxDynamicSharedMemorySize, (int)smemP);

    dim3 gG(8, 4, 4);                            // 128 CTAs x 512 thr
    uv_gemm_kernel<<<gG, 512, smemG>>>(he, W0w);

    reduce_kernel<<<512, 256>>>(W0b);

    pairwise_kernel<<<N / 4, 512, smemP>>>(W1w); // 128 CTAs x 512 thr

    dim3 gC(16, 16);                             // 256 CTAs x 256 thr
    out_gemm_kernel<<<gC, 256>>>(he, out);
}

// round 15
// speedup vs baseline: 1.1198x; 1.1198x over previous
#include <cuda_runtime.h>

#define N 512
#define D 512

__device__ float g_u[N * D];             // u[i][h]
__device__ float g_vT[D * N];            // v^T[h][j] (+W0_b folded)
__device__ float g_a[N * N];             // softmax rows
__device__ float g_heT[D * D];           // he transposed [c][k]
__device__ float g_part[4 * N * 1024];   // uv k-split partials
__device__ float g_part2[8 * N * D];     // out k-split partials

typedef unsigned long long u64;

__device__ __forceinline__ void fma2(u64& d, u64 a, u64 b) {
    asm("fma.rn.f32x2 %0, %1, %2, %3;" : "=l"(d) : "l"(a), "l"(b), "l"(d));
}
__device__ __forceinline__ u64 add2(u64 a, u64 b) {
    u64 d; asm("add.rn.f32x2 %0, %1, %2;" : "=l"(d) : "l"(a), "l"(b)); return d;
}
__device__ __forceinline__ u64 pk(float x, float y) {
    u64 d; asm("mov.b64 %0, {%1, %2};" : "=l"(d) : "f"(x), "f"(y)); return d;
}
__device__ __forceinline__ float2 upk(u64 v) {
    float2 d; asm("mov.b64 {%0, %1}, %2;" : "=f"(d.x), "=f"(d.y) : "l"(v)); return d;
}
__device__ __forceinline__ void cpa16(float* dst, const float* src) {
    unsigned sa = (unsigned)__cvta_generic_to_shared(dst);
    asm volatile("cp.async.cg.shared.global [%0], [%1], 16;" :: "r"(sa), "l"(src));
}

// ---------------------------------------------------------------------------
// GEMM core layout: 128x128 tile, 512 threads (16 warps). Warp w owns rows
// 8w..8w+7 (A reads = warp-uniform LDS.128 broadcasts); lane owns cols
// lane+32c, c<4 (B reads = exactly-4-phase conflict-free LDS.128 at stride 36).
// Per 4k: 12 LDS feed 64 fma2 -> fma-pipe-bound.
// ---------------------------------------------------------------------------
#define GST 36

// Kernel 1: fused u|v NT-GEMM, k-split 4. grid (8 n-tiles, 4 i-tiles, 4 kz).
__global__ __launch_bounds__(512) void uv_gemm_kernel(
    const float* __restrict__ he, const float* __restrict__ W)
{
    extern __shared__ float sm[];
    float* as = sm;                    // [2][128*GST]
    float* bs = sm + 2 * 128 * GST;

    const int n0 = blockIdx.x * 128;
    const int i0 = blockIdx.y * 128;
    const int kz = blockIdx.z;
    const int kbase = kz * 128;
    const int koff = (n0 >= 512) ? 512 : 0;
    const int nr0 = n0 & 511;
    const int tid = threadIdx.x;
    const int lane = tid & 31;
    const int warp = tid >> 5;

    // prologue chunk 0: 1024 f4 per matrix, 2 per thread
    #pragma unroll
    for (int q = 0; q < 2; q++) {
        const int f = tid + 512 * q;
        const int r = f >> 3, kq = (f & 7) << 2;
        cpa16(&as[r * GST + kq], &he[(size_t)(i0 + r) * D + kbase + kq]);
        cpa16(&bs[r * GST + kq], &W[(size_t)(nr0 + r) * 1024 + koff + kbase + kq]);
    }
    asm volatile("cp.async.commit_group;");

    u64 acc[8][4] = {};

    for (int ch = 0; ch < 4; ch++) {
        if (ch + 1 < 4) {
            float* ad = as + ((ch + 1) & 1) * 128 * GST;
            float* bd = bs + ((ch + 1) & 1) * 128 * GST;
            const int kc = kbase + (ch + 1) * 32;
            #pragma unroll
            for (int q = 0; q < 2; q++) {
                const int f = tid + 512 * q;
                const int r = f >> 3, kq = (f & 7) << 2;
                cpa16(&ad[r * GST + kq], &he[(size_t)(i0 + r) * D + kc + kq]);
                cpa16(&bd[r * GST + kq], &W[(size_t)(nr0 + r) * 1024 + koff + kc + kq]);
            }
            asm volatile("cp.async.commit_group;");
            asm volatile("cp.async.wait_group 1;");
        } else {
            asm volatile("cp.async.wait_group 0;");
        }
        __syncthreads();

        const float* ab = as + (ch & 1) * 128 * GST;
        const float* bb = bs + (ch & 1) * 128 * GST;
        #pragma unroll
        for (int kk = 0; kk < 32; kk += 4) {
            ulonglong2 av[8], bv[4];
            #pragma unroll
            for (int r = 0; r < 8; r++)      // warp-uniform broadcast
                av[r] = *(const ulonglong2*)&ab[(8 * warp + r) * GST + kk];
            #pragma unroll
            for (int c = 0; c < 4; c++)      // conflict-free 4-phase
                bv[c] = *(const ulonglong2*)&bb[(lane + 32 * c) * GST + kk];
            #pragma unroll
            for (int r = 0; r < 8; r++)
                #pragma unroll
                for (int c = 0; c < 4; c++) {
                    fma2(acc[r][c], av[r].x, bv[c].x);
                    fma2(acc[r][c], av[r].y, bv[c].y);
                }
        }
        __syncthreads();
    }

    #pragma unroll
    for (int r = 0; r < 8; r++) {
        const size_t row = i0 + 8 * warp + r;
        float* dst = g_part + (size_t)kz * (N * 1024) + row * 1024 + n0;
        #pragma unroll
        for (int c = 0; c < 4; c++) {
            float2 f = upk(acc[r][c]);
            dst[lane + 32 * c] = f.x + f.y;
        }
    }
}

// Kernel 2: reduce uv partials -> g_u, g_vT (+bias). grid 512 x 256.
__global__ __launch_bounds__(256) void reduce_kernel(const float* __restrict__ b)
{
    const int idx4 = blockIdx.x * 256 + threadIdx.x;   // 0..131071
    float4 s = *(const float4*)&g_part[(size_t)idx4 * 4];
    #pragma unroll
    for (int kz = 1; kz < 4; kz++) {
        float4 p = *(const float4*)&g_part[(size_t)kz * (N * 1024) + (size_t)idx4 * 4];
        s.x += p.x; s.y += p.y; s.z += p.z; s.w += p.w;
    }
    const int base = idx4 * 4;
    const int i = base >> 10;
    const int h = base & 1023;
    if (h < 512) {
        *(float4*)&g_u[(size_t)i * D + h] = s;
    } else {
        const int hh = h - 512;
        g_vT[(size_t)(hh + 0) * N + i] = s.x + b[hh + 0];
        g_vT[(size_t)(hh + 1) * N + i] = s.y + b[hh + 1];
        g_vT[(size_t)(hh + 2) * N + i] = s.z + b[hh + 2];
        g_vT[(size_t)(hh + 3) * N + i] = s.w + b[hh + 3];
    }
}

// Kernel 3: transpose he -> g_heT[c][k]. grid (16,16) x 256.
__global__ __launch_bounds__(256) void transpose_kernel(const float* __restrict__ he)
{
    __shared__ float t[32][33];
    const int k0 = blockIdx.x * 32;
    const int c0 = blockIdx.y * 32;
    const int r = threadIdx.x >> 3;
    const int q = (threadIdx.x & 7) << 2;

    float4 v = *(const float4*)&he[(size_t)(k0 + r) * D + c0 + q];
    t[r][q + 0] = v.x; t[r][q + 1] = v.y; t[r][q + 2] = v.z; t[r][q + 3] = v.w;
    __syncthreads();

    float4 o = make_float4(t[q + 0][r], t[q + 1][r], t[q + 2][r], t[q + 3][r]);
    *(float4*)&g_heT[(size_t)(c0 + r) * D + k0 + q] = o;
}

// ---------------------------------------------------------------------------
// Kernel 4: pairwise + softmax. CTA = 4 i x 512 j, 256 threads (thread =
// 4 i x 1 j-pair). relu via packed-abs: relu(x)*w = (x+|x|)*(w/2);
// |x| = AND with 0x7fffffff mask (alu pipe, no pack/unpack MOVs).
// v staged via cp.async double-buffer; u/w broadcast LDS.128.
// ---------------------------------------------------------------------------
#define PHCH 8

__global__ __launch_bounds__(256) void pairwise_kernel(
    const float* __restrict__ w1)
{
    extern __shared__ float sm[];
    float* v_s   = sm;                              // [2][PHCH][512]
    u64*  u2s    = (u64*)(sm + 2 * PHCH * 512);     // [4*512] {u,u}
    u64*  w2h    = u2s + 4 * 512;                   // [512] {w/2,w/2}
    float* p_s   = (float*)(w2h + 512);             // [4][512]
    float* inv_s = p_s + 4 * 512;                   // [4]

    const int tid = threadIdx.x;
    const int i0 = blockIdx.x * 4;
    const u64 ABS2 = 0x7fffffff7fffffffull;

    // stage u (4 rows) duplicated, w1 duplicated and pre-halved
    {
        const float4* usrc = (const float4*)(g_u + (size_t)i0 * D);
        #pragma unroll
        for (int e = 0; e < 2; e++) {
            const int m = tid + 256 * e;            // 0..511 f4
            float4 f = usrc[m];
            u2s[m * 4 + 0] = pk(f.x, f.x);
            u2s[m * 4 + 1] = pk(f.y, f.y);
            u2s[m * 4 + 2] = pk(f.z, f.z);
            u2s[m * 4 + 3] = pk(f.w, f.w);
        }
        if (tid < 128) {
            float4 w = ((const float4*)w1)[tid];
            w2h[tid * 4 + 0] = pk(0.5f * w.x, 0.5f * w.x);
            w2h[tid * 4 + 1] = pk(0.5f * w.y, 0.5f * w.y);
            w2h[tid * 4 + 2] = pk(0.5f * w.z, 0.5f * w.z);
            w2h[tid * 4 + 3] = pk(0.5f * w.w, 0.5f * w.w);
        }
    }

    // prologue: v chunk 0 (PHCH x 512 = 1024 f4, 4 per thread)
    #pragma unroll
    for (int q = 0; q < 4; q++) {
        const int m = tid + 256 * q;
        const int r = m >> 7, c4 = (m & 127) << 2;
        cpa16(v_s + r * 512 + c4, g_vT + (size_t)r * N + c4);
    }
    asm volatile("cp.async.commit_group;");

    u64 acc[4] = {};

    for (int ch = 0; ch < D / PHCH; ch++) {
        if (ch + 1 < D / PHCH) {
            float* buf = v_s + ((ch + 1) & 1) * PHCH * 512;
            const float* src = g_vT + (size_t)(ch + 1) * PHCH * N;
            #pragma unroll
            for (int q = 0; q < 4; q++) {
                const int m = tid + 256 * q;
                const int r = m >> 7, c4 = (m & 127) << 2;
                cpa16(buf + r * 512 + c4, src + (size_t)r * N + c4);
            }
            asm volatile("cp.async.commit_group;");
            asm volatile("cp.async.wait_group 1;");
        } else {
            asm volatile("cp.async.wait_group 0;");
        }
        __syncthreads();

        const float* vb = v_s + (ch & 1) * PHCH * 512;
        const int g0 = ch * PHCH;
        #pragma unroll
        for (int hh = 0; hh < PHCH; hh += 2) {
            const u64 v0 = *(const u64*)&vb[hh * 512 + 2 * tid];
            const u64 v1 = *(const u64*)&vb[(hh + 1) * 512 + 2 * tid];
            const ulonglong2 ww = *(const ulonglong2*)&w2h[g0 + hh];
            #pragma unroll
            for (int i = 0; i < 4; i++) {
                const ulonglong2 uu = *(const ulonglong2*)&u2s[i * 512 + g0 + hh];
                u64 t0 = add2(uu.x, v0);
                u64 t1 = add2(uu.y, v1);
                t0 = add2(t0, t0 & ABS2);        // x + |x| = 2*relu(x)
                t1 = add2(t1, t1 & ABS2);
                fma2(acc[i], t0, ww.x);          // * (w/2)
                fma2(acc[i], t1, ww.y);
            }
        }
        __syncthreads();
    }

    #pragma unroll
    for (int i = 0; i < 4; i++)
        ((u64*)(p_s + i * 512))[tid] = acc[i];
    __syncthreads();

    // softmax: warps 0..3 handle rows 0..3
    const int warp = tid >> 5, lane = tid & 31;
    if (warp < 4) {
        float* prow = p_s + warp * 512;
        float m = -1e30f;
        for (int j = lane; j < N; j += 32) m = fmaxf(m, prow[j]);
        #pragma unroll
        for (int o = 16; o; o >>= 1) m = fmaxf(m, __shfl_xor_sync(0xffffffffu, m, o));
        float s = 0.f;
        for (int j = lane; j < N; j += 32) {
            float e = __expf(prow[j] - m);
            prow[j] = e;
            s += e;
        }
        #pragma unroll
        for (int o = 16; o; o >>= 1) s += __shfl_xor_sync(0xffffffffu, s, o);
        if (lane == 0) inv_s[warp] = 1.f / s;
    }
    __syncthreads();

    #pragma unroll
    for (int e = 0; e < 2; e++) {
        const int m = tid + 256 * e;
        const int i = m >> 7, jj = m & 127;
        float4 v = ((const float4*)(p_s + i * 512))[jj];
        const float s = inv_s[i];
        v.x *= s; v.y *= s; v.z *= s; v.w *= s;
        ((float4*)(g_a + (size_t)(i0 + i) * N))[jj] = v;
    }
}

// ---------------------------------------------------------------------------
// Kernel 5: out NT-GEMM vs g_heT, k-split 8. Same core as uv. grid (4,4,8).
// ---------------------------------------------------------------------------
__global__ __launch_bounds__(512) void out_gemm_kernel(void)
{
    extern __shared__ float sm[];
    float* as = sm;
    float* bs = sm + 2 * 128 * GST;

    const int c0 = blockIdx.x * 128;
    const int i0 = blockIdx.y * 128;
    const int kz = blockIdx.z;
    const int kbase = kz * 64;
    const int tid = threadIdx.x;
    const int lane = tid & 31;
    const int warp = tid >> 5;

    #pragma unroll
    for (int q = 0; q < 2; q++) {
        const int f = tid + 512 * q;
        const int r = f >> 3, kq = (f & 7) << 2;
        cpa16(&as[r * GST + kq], &g_a[(size_t)(i0 + r) * N + kbase + kq]);
        cpa16(&bs[r * GST + kq], &g_heT[(size_t)(c0 + r) * D + kbase + kq]);
    }
    asm volatile("cp.async.commit_group;");

    u64 acc[8][4] = {};

    for (int ch = 0; ch < 2; ch++) {
        if (ch + 1 < 2) {
            float* ad = as + 128 * GST;
            float* bd = bs + 128 * GST;
            const int kc = kbase + 32;
            #pragma unroll
            for (int q = 0; q < 2; q++) {
                const int f = tid + 512 * q;
                const int r = f >> 3, kq = (f & 7) << 2;
                cpa16(&ad[r * GST + kq], &g_a[(size_t)(i0 + r) * N + kc + kq]);
                cpa16(&bd[r * GST + kq], &g_heT[(size_t)(c0 + r) * D + kc + kq]);
            }
            asm volatile("cp.async.commit_group;");
            asm volatile("cp.async.wait_group 1;");
        } else {
            asm volatile("cp.async.wait_group 0;");
        }
        __syncthreads();

        const float* ab = as + (ch & 1) * 128 * GST;
        const float* bb = bs + (ch & 1) * 128 * GST;
        #pragma unroll
        for (int kk = 0; kk < 32; kk += 4) {
            ulonglong2 av[8], bv[4];
            #pragma unroll
            for (int r = 0; r < 8; r++)
                av[r] = *(const ulonglong2*)&ab[(8 * warp + r) * GST + kk];
            #pragma unroll
            for (int c = 0; c < 4; c++)
                bv[c] = *(const ulonglong2*)&bb[(lane + 32 * c) * GST + kk];
            #pragma unroll
            for (int r = 0; r < 8; r++)
                #pragma unroll
                for (int c = 0; c < 4; c++) {
                    fma2(acc[r][c], av[r].x, bv[c].x);
                    fma2(acc[r][c], av[r].y, bv[c].y);
                }
        }
        __syncthreads();
    }

    #pragma unroll
    for (int r = 0; r < 8; r++) {
        const size_t row = i0 + 8 * warp + r;
        float* dst = g_part2 + (size_t)kz * (N * D) + row * D + c0;
        #pragma unroll
        for (int c = 0; c < 4; c++) {
            float2 f = upk(acc[r][c]);
            dst[lane + 32 * c] = f.x + f.y;
        }
    }
}

// Kernel 6: reduce out partials -> d_out. grid 256 x 256.
__global__ __launch_bounds__(256) void reduce2_kernel(float* __restrict__ out)
{
    const int idx4 = blockIdx.x * 256 + threadIdx.x;   // 0..65535
    float4 s = *(const float4*)&g_part2[(size_t)idx4 * 4];
    #pragma unroll
    for (int kz = 1; kz < 8; kz++) {
        float4 p = *(const float4*)&g_part2[(size_t)kz * (N * D) + (size_t)idx4 * 4];
        s.x += p.x; s.y += p.y; s.z += p.z; s.w += p.w;
    }
    ((float4*)out)[idx4] = s;
}

// ---------------------------------------------------------------------------
extern "C" void kernel_launch(void* const* d_in, const int* in_sizes, int n_in,
                              void* d_out, int out_size)
{
    const float* he  = (const float*)d_in[0];   // (512, 512)
    const float* W0w = (const float*)d_in[1];   // (512, 1024)
    const float* W0b = (const float*)d_in[2];   // (512,)
    const float* W1w = (const float*)d_in[3];   // (1, 512)
    // d_in[4] = W1_b: softmax shift-invariant -> unused
    float* out = (float*)d_out;

    const size_t smemG = (size_t)(4 * 128 * GST) * sizeof(float);     // ~73.7KB
    const size_t smemP = (size_t)(2 * PHCH * 512) * sizeof(float)
                       + (size_t)(4 * 512 + 512) * sizeof(u64)
                       + (size_t)(4 * 512 + 8) * sizeof(float);
    cudaFuncSetAttribute(uv_gemm_kernel,
                         cudaFuncAttributeMaxDynamicSharedMemorySize, (int)smemG);
    cudaFuncSetAttribute(out_gemm_kernel,
                         cudaFuncAttributeMaxDynamicSharedMemorySize, (int)smemG);
    cudaFuncSetAttribute(pairwise_kernel,
                         cudaFuncAttributeMaxDynamicSharedMemorySize, (int)smemP);

    dim3 gG(8, 4, 4);                            // 128 CTAs x 512 thr
    uv_gemm_kernel<<<gG, 512, smemG>>>(he, W0w);

    reduce_kernel<<<512, 256>>>(W0b);

    dim3 gT(16, 16);
    transpose_kernel<<<gT, 256>>>(he);

    pairwise_kernel<<<N / 4, 256, smemP>>>(W1w); // 128 CTAs x 256 thr

    dim3 gO(4, 4, 8);                            // 128 CTAs x 512 thr
    out_gemm_kernel<<<gO, 512, smemG>>>();

    reduce2_kernel<<<256, 256>>>(out);
}

// round 17
// speedup vs baseline: 1.1546x; 1.0310x over previous
#include <cuda_runtime.h>

#define N 512
#define D 512

__device__ float g_u[N * D];             // u[i][h]
__device__ float g_vT[D * N];            // v^T[h][j] (+W0_b folded)
__device__ float g_p[N * N];             // raw logits
__device__ float g_a[N * N];             // softmax rows
__device__ float g_heT[D * D];           // he transposed [c][k]
__device__ float g_part[4 * N * 1024];   // uv k-split partials
__device__ float g_part2[8 * N * D];     // out k-split partials

typedef unsigned long long u64;

__device__ __forceinline__ void fma2(u64& d, u64 a, u64 b) {
    asm("fma.rn.f32x2 %0, %1, %2, %3;" : "=l"(d) : "l"(a), "l"(b), "l"(d));
}
__device__ __forceinline__ u64 add2(u64 a, u64 b) {
    u64 d; asm("add.rn.f32x2 %0, %1, %2;" : "=l"(d) : "l"(a), "l"(b)); return d;
}
__device__ __forceinline__ u64 pk(float x, float y) {
    u64 d; asm("mov.b64 %0, {%1, %2};" : "=l"(d) : "f"(x), "f"(y)); return d;
}
__device__ __forceinline__ float2 upk(u64 v) {
    float2 d; asm("mov.b64 {%0, %1}, %2;" : "=f"(d.x), "=f"(d.y) : "l"(v)); return d;
}
__device__ __forceinline__ void cpa16(float* dst, const float* src) {
    unsigned sa = (unsigned)__cvta_generic_to_shared(dst);
    asm volatile("cp.async.cg.shared.global [%0], [%1], 16;" :: "r"(sa), "l"(src));
}

// ---------------------------------------------------------------------------
// GEMM core: 128x128 tile, 512 threads. Warp owns 8 rows (A = warp-uniform
// LDS.128 broadcasts); lane owns cols lane+32c (B = 4-phase conflict-free).
// ---------------------------------------------------------------------------
#define GST 36

// Kernel 1: fused u|v NT-GEMM, k-split 4. grid (8,4,4) = 128 CTAs.
__global__ __launch_bounds__(512) void uv_gemm_kernel(
    const float* __restrict__ he, const float* __restrict__ W)
{
    extern __shared__ float sm[];
    float* as = sm;                    // [2][128*GST]
    float* bs = sm + 2 * 128 * GST;

    const int n0 = blockIdx.x * 128;
    const int i0 = blockIdx.y * 128;
    const int kz = blockIdx.z;
    const int kbase = kz * 128;
    const int koff = (n0 >= 512) ? 512 : 0;
    const int nr0 = n0 & 511;
    const int tid = threadIdx.x;
    const int lane = tid & 31;
    const int warp = tid >> 5;

    #pragma unroll
    for (int q = 0; q < 2; q++) {
        const int f = tid + 512 * q;
        const int r = f >> 3, kq = (f & 7) << 2;
        cpa16(&as[r * GST + kq], &he[(size_t)(i0 + r) * D + kbase + kq]);
        cpa16(&bs[r * GST + kq], &W[(size_t)(nr0 + r) * 1024 + koff + kbase + kq]);
    }
    asm volatile("cp.async.commit_group;");

    u64 acc[8][4] = {};

    for (int ch = 0; ch < 4; ch++) {
        if (ch + 1 < 4) {
            float* ad = as + ((ch + 1) & 1) * 128 * GST;
            float* bd = bs + ((ch + 1) & 1) * 128 * GST;
            const int kc = kbase + (ch + 1) * 32;
            #pragma unroll
            for (int q = 0; q < 2; q++) {
                const int f = tid + 512 * q;
                const int r = f >> 3, kq = (f & 7) << 2;
                cpa16(&ad[r * GST + kq], &he[(size_t)(i0 + r) * D + kc + kq]);
                cpa16(&bd[r * GST + kq], &W[(size_t)(nr0 + r) * 1024 + koff + kc + kq]);
            }
            asm volatile("cp.async.commit_group;");
            asm volatile("cp.async.wait_group 1;");
        } else {
            asm volatile("cp.async.wait_group 0;");
        }
        __syncthreads();

        const float* ab = as + (ch & 1) * 128 * GST;
        const float* bb = bs + (ch & 1) * 128 * GST;
        #pragma unroll
        for (int kk = 0; kk < 32; kk += 4) {
            ulonglong2 av[8], bv[4];
            #pragma unroll
            for (int r = 0; r < 8; r++)
                av[r] = *(const ulonglong2*)&ab[(8 * warp + r) * GST + kk];
            #pragma unroll
            for (int c = 0; c < 4; c++)
                bv[c] = *(const ulonglong2*)&bb[(lane + 32 * c) * GST + kk];
            #pragma unroll
            for (int r = 0; r < 8; r++)
                #pragma unroll
                for (int c = 0; c < 4; c++) {
                    fma2(acc[r][c], av[r].x, bv[c].x);
                    fma2(acc[r][c], av[r].y, bv[c].y);
                }
        }
        __syncthreads();
    }

    #pragma unroll
    for (int r = 0; r < 8; r++) {
        const size_t row = i0 + 8 * warp + r;
        float* dst = g_part + (size_t)kz * (N * 1024) + row * 1024 + n0;
        #pragma unroll
        for (int c = 0; c < 4; c++) {
            float2 f = upk(acc[r][c]);
            dst[lane + 32 * c] = f.x + f.y;
        }
    }
}

// Kernel 2: reduce uv partials -> g_u, g_vT (+bias). grid 512 x 256.
__global__ __launch_bounds__(256) void reduce_kernel(const float* __restrict__ b)
{
    const int idx4 = blockIdx.x * 256 + threadIdx.x;
    float4 s = *(const float4*)&g_part[(size_t)idx4 * 4];
    #pragma unroll
    for (int kz = 1; kz < 4; kz++) {
        float4 p = *(const float4*)&g_part[(size_t)kz * (N * 1024) + (size_t)idx4 * 4];
        s.x += p.x; s.y += p.y; s.z += p.z; s.w += p.w;
    }
    const int base = idx4 * 4;
    const int i = base >> 10;
    const int h = base & 1023;
    if (h < 512) {
        *(float4*)&g_u[(size_t)i * D + h] = s;
    } else {
        const int hh = h - 512;
        g_vT[(size_t)(hh + 0) * N + i] = s.x + b[hh + 0];
        g_vT[(size_t)(hh + 1) * N + i] = s.y + b[hh + 1];
        g_vT[(size_t)(hh + 2) * N + i] = s.z + b[hh + 2];
        g_vT[(size_t)(hh + 3) * N + i] = s.w + b[hh + 3];
    }
}

// Kernel 3: transpose he -> g_heT[c][k]. grid (16,16) x 256.
__global__ __launch_bounds__(256) void transpose_kernel(const float* __restrict__ he)
{
    __shared__ float t[32][33];
    const int k0 = blockIdx.x * 32;
    const int c0 = blockIdx.y * 32;
    const int r = threadIdx.x >> 3;
    const int q = (threadIdx.x & 7) << 2;

    float4 v = *(const float4*)&he[(size_t)(k0 + r) * D + c0 + q];
    t[r][q + 0] = v.x; t[r][q + 1] = v.y; t[r][q + 2] = v.z; t[r][q + 3] = v.w;
    __syncthreads();

    float4 o = make_float4(t[q + 0][r], t[q + 1][r], t[q + 2][r], t[q + 3][r]);
    *(float4*)&g_heT[(size_t)(c0 + r) * D + k0 + q] = o;
}

// ---------------------------------------------------------------------------
// Kernel 4: pairwise logits only. CTA = 16 i x 128 j (grid 4 j-tiles x 32
// i-tiles = 128 CTAs), 512 threads (16 warps; thread = 2 i x 1 j-pair).
// v tile (32h x 128j) cp.async double-buffered; u/w duplicated {x,x} u64
// broadcasts; relu via packed-abs AND trick. Writes raw p to g_p (STG.64).
// ---------------------------------------------------------------------------
#define PCH 32

__global__ __launch_bounds__(512) void pairwise_kernel(
    const float* __restrict__ w1)
{
    extern __shared__ float sm[];
    float* v_s = sm;                            // [2][PCH][128]
    u64*  u2s  = (u64*)(sm + 2 * PCH * 128);    // [16*512] {u,u}
    u64*  w2h  = u2s + 16 * 512;                // [512] {w/2,w/2}

    const int tid = threadIdx.x;
    const int j0 = blockIdx.x * 128;
    const int i0 = blockIdx.y * 16;
    const int jp = tid & 63;                    // j-pair: j0 + 2jp, +1
    const int g = tid >> 6;                     // 0..7 -> i rows 2g, 2g+1
    const u64 ABS2 = 0x7fffffff7fffffffull;

    // stage u (16 rows) duplicated + w1 duplicated/halved
    {
        const float4* usrc = (const float4*)(g_u + (size_t)i0 * D);
        #pragma unroll
        for (int q = 0; q < 4; q++) {
            const int m = tid + 512 * q;        // 0..2047 f4
            float4 f = usrc[m];
            u2s[m * 4 + 0] = pk(f.x, f.x);
            u2s[m * 4 + 1] = pk(f.y, f.y);
            u2s[m * 4 + 2] = pk(f.z, f.z);
            u2s[m * 4 + 3] = pk(f.w, f.w);
        }
        if (tid < 128) {
            float4 w = ((const float4*)w1)[tid];
            w2h[tid * 4 + 0] = pk(0.5f * w.x, 0.5f * w.x);
            w2h[tid * 4 + 1] = pk(0.5f * w.y, 0.5f * w.y);
            w2h[tid * 4 + 2] = pk(0.5f * w.z, 0.5f * w.z);
            w2h[tid * 4 + 3] = pk(0.5f * w.w, 0.5f * w.w);
        }
    }

    // prologue: v chunk 0 (PCH x 128 = 1024 f4, 2 per thread)
    #pragma unroll
    for (int q = 0; q < 2; q++) {
        const int m = tid + 512 * q;
        const int r = m >> 5, c4 = (m & 31) << 2;
        cpa16(v_s + r * 128 + c4, g_vT + (size_t)r * N + j0 + c4);
    }
    asm volatile("cp.async.commit_group;");

    u64 acc[2] = {};

    for (int ch = 0; ch < D / PCH; ch++) {
        if (ch + 1 < D / PCH) {
            float* buf = v_s + ((ch + 1) & 1) * PCH * 128;
            const float* src = g_vT + (size_t)(ch + 1) * PCH * N + j0;
            #pragma unroll
            for (int q = 0; q < 2; q++) {
                const int m = tid + 512 * q;
                const int r = m >> 5, c4 = (m & 31) << 2;
                cpa16(buf + r * 128 + c4, src + (size_t)r * N + c4);
            }
            asm volatile("cp.async.commit_group;");
            asm volatile("cp.async.wait_group 1;");
        } else {
            asm volatile("cp.async.wait_group 0;");
        }
        __syncthreads();

        const float* vb = v_s + (ch & 1) * PCH * 128;
        const int g0 = ch * PCH;
        #pragma unroll
        for (int hh = 0; hh < PCH; hh += 2) {
            const u64 v0 = *(const u64*)&vb[hh * 128 + 2 * jp];
            const u64 v1 = *(const u64*)&vb[(hh + 1) * 128 + 2 * jp];
            const ulonglong2 ww = *(const ulonglong2*)&w2h[g0 + hh];
            #pragma unroll
            for (int ii = 0; ii < 2; ii++) {
                const ulonglong2 uu = *(const ulonglong2*)&u2s[(2 * g + ii) * 512 + g0 + hh];
                u64 t0 = add2(uu.x, v0);
                u64 t1 = add2(uu.y, v1);
                t0 = add2(t0, t0 & ABS2);        // x + |x| = 2*relu(x)
                t1 = add2(t1, t1 & ABS2);
                fma2(acc[ii], t0, ww.x);         // * (w/2)
                fma2(acc[ii], t1, ww.y);
            }
        }
        __syncthreads();
    }

    #pragma unroll
    for (int ii = 0; ii < 2; ii++) {
        float2 f = upk(acc[ii]);
        *(float2*)&g_p[(size_t)(i0 + 2 * g + ii) * N + j0 + 2 * jp] = f;
    }
}

// ---------------------------------------------------------------------------
// Kernel 5: row softmax g_p -> g_a. Warp per row; grid 32 x 512 threads.
// ---------------------------------------------------------------------------
__global__ __launch_bounds__(512) void softmax_kernel(void)
{
    const int warp = threadIdx.x >> 5, lane = threadIdx.x & 31;
    const int row = blockIdx.x * 16 + warp;
    const float4* src = (const float4*)(g_p + (size_t)row * N);
    float4* dst = (float4*)(g_a + (size_t)row * N);

    float4 v[4];
    float m = -1e30f;
    #pragma unroll
    for (int q = 0; q < 4; q++) {
        v[q] = src[lane + 32 * q];
        m = fmaxf(m, fmaxf(fmaxf(v[q].x, v[q].y), fmaxf(v[q].z, v[q].w)));
    }
    #pragma unroll
    for (int o = 16; o; o >>= 1) m = fmaxf(m, __shfl_xor_sync(0xffffffffu, m, o));

    float s = 0.f;
    #pragma unroll
    for (int q = 0; q < 4; q++) {
        v[q].x = __expf(v[q].x - m); v[q].y = __expf(v[q].y - m);
        v[q].z = __expf(v[q].z - m); v[q].w = __expf(v[q].w - m);
        s += (v[q].x + v[q].y) + (v[q].z + v[q].w);
    }
    #pragma unroll
    for (int o = 16; o; o >>= 1) s += __shfl_xor_sync(0xffffffffu, s, o);
    const float inv = 1.f / s;

    #pragma unroll
    for (int q = 0; q < 4; q++) {
        v[q].x *= inv; v[q].y *= inv; v[q].z *= inv; v[q].w *= inv;
        dst[lane + 32 * q] = v[q];
    }
}

// ---------------------------------------------------------------------------
// Kernel 6: out NT-GEMM vs g_heT, k-split 8. grid (4,4,8) = 128 CTAs.
// ---------------------------------------------------------------------------
__global__ __launch_bounds__(512) void out_gemm_kernel(void)
{
    extern __shared__ float sm[];
    float* as = sm;
    float* bs = sm + 2 * 128 * GST;

    const int c0 = blockIdx.x * 128;
    const int i0 = blockIdx.y * 128;
    const int kz = blockIdx.z;
    const int kbase = kz * 64;
    const int tid = threadIdx.x;
    const int lane = tid & 31;
    const int warp = tid >> 5;

    #pragma unroll
    for (int q = 0; q < 2; q++) {
        const int f = tid + 512 * q;
        const int r = f >> 3, kq = (f & 7) << 2;
        cpa16(&as[r * GST + kq], &g_a[(size_t)(i0 + r) * N + kbase + kq]);
        cpa16(&bs[r * GST + kq], &g_heT[(size_t)(c0 + r) * D + kbase + kq]);
    }
    asm volatile("cp.async.commit_group;");

    u64 acc[8][4] = {};

    for (int ch = 0; ch < 2; ch++) {
        if (ch + 1 < 2) {
            float* ad = as + 128 * GST;
            float* bd = bs + 128 * GST;
            const int kc = kbase + 32;
            #pragma unroll
            for (int q = 0; q < 2; q++) {
                const int f = tid + 512 * q;
                const int r = f >> 3, kq = (f & 7) << 2;
                cpa16(&ad[r * GST + kq], &g_a[(size_t)(i0 + r) * N + kc + kq]);
                cpa16(&bd[r * GST + kq], &g_heT[(size_t)(c0 + r) * D + kc + kq]);
            }
            asm volatile("cp.async.commit_group;");
            asm volatile("cp.async.wait_group 1;");
        } else {
            asm volatile("cp.async.wait_group 0;");
        }
        __syncthreads();

        const float* ab = as + (ch & 1) * 128 * GST;
        const float* bb = bs + (ch & 1) * 128 * GST;
        #pragma unroll
        for (int kk = 0; kk < 32; kk += 4) {
            ulonglong2 av[8], bv[4];
            #pragma unroll
            for (int r = 0; r < 8; r++)
                av[r] = *(const ulonglong2*)&ab[(8 * warp + r) * GST + kk];
            #pragma unroll
            for (int c = 0; c < 4; c++)
                bv[c] = *(const ulonglong2*)&bb[(lane + 32 * c) * GST + kk];
            #pragma unroll
            for (int r = 0; r < 8; r++)
                #pragma unroll
                for (int c = 0; c < 4; c++) {
                    fma2(acc[r][c], av[r].x, bv[c].x);
                    fma2(acc[r][c], av[r].y, bv[c].y);
                }
        }
        __syncthreads();
    }

    #pragma unroll
    for (int r = 0; r < 8; r++) {
        const size_t row = i0 + 8 * warp + r;
        float* dst = g_part2 + (size_t)kz * (N * D) + row * D + c0;
        #pragma unroll
        for (int c = 0; c < 4; c++) {
            float2 f = upk(acc[r][c]);
            dst[lane + 32 * c] = f.x + f.y;
        }
    }
}

// Kernel 7: reduce out partials -> d_out. grid 256 x 256.
__global__ __launch_bounds__(256) void reduce2_kernel(float* __restrict__ out)
{
    const int idx4 = blockIdx.x * 256 + threadIdx.x;
    float4 s = *(const float4*)&g_part2[(size_t)idx4 * 4];
    #pragma unroll
    for (int kz = 1; kz < 8; kz++) {
        float4 p = *(const float4*)&g_part2[(size_t)kz * (N * D) + (size_t)idx4 * 4];
        s.x += p.x; s.y += p.y; s.z += p.z; s.w += p.w;
    }
    ((float4*)out)[idx4] = s;
}

// ---------------------------------------------------------------------------
extern "C" void kernel_launch(void* const* d_in, const int* in_sizes, int n_in,
                              void* d_out, int out_size)
{
    const float* he  = (const float*)d_in[0];   // (512, 512)
    const float* W0w = (const float*)d_in[1];   // (512, 1024)
    const float* W0b = (const float*)d_in[2];   // (512,)
    const float* W1w = (const float*)d_in[3];   // (1, 512)
    // d_in[4] = W1_b: softmax shift-invariant -> unused
    float* out = (float*)d_out;

    const size_t smemG = (size_t)(4 * 128 * GST) * sizeof(float);       // ~73.7KB
    const size_t smemP = (size_t)(2 * PCH * 128) * sizeof(float)        // v 32KB
                       + (size_t)(16 * 512 + 512) * sizeof(u64);        // u 64KB + w 4KB
    cudaFuncSetAttribute(uv_gemm_kernel,
                         cudaFuncAttributeMaxDynamicSharedMemorySize, (int)smemG);
    cudaFuncSetAttribute(out_gemm_kernel,
                         cudaFuncAttributeMaxDynamicSharedMemorySize, (int)smemG);
    cudaFuncSetAttribute(pairwise_kernel,
                         cudaFuncAttributeMaxDynamicSharedMemorySize, (int)smemP);

    dim3 gG(8, 4, 4);                            // 128 CTAs x 512 thr
    uv_gemm_kernel<<<gG, 512, smemG>>>(he, W0w);

    reduce_kernel<<<512, 256>>>(W0b);

    dim3 gT(16, 16);
    transpose_kernel<<<gT, 256>>>(he);

    dim3 gP(4, 32);                              // 128 CTAs x 512 thr
    pairwise_kernel<<<gP, 512, smemP>>>(W1w);

    softmax_kernel<<<32, 512>>>();

    dim3 gO(4, 4, 8);                            // 128 CTAs x 512 thr
    out_gemm_kernel<<<gO, 512, smemG>>>();

    reduce2_kernel<<<256, 256>>>(out);
}